// round 1
// baseline (speedup 1.0000x reference)
#include <cuda_runtime.h>
#include <cuda_bf16.h>
#include <limits.h>

// StreamingRhythmProjector on GB300.
// One block per row (B rows), BS threads, ITEMS elements per thread held in
// registers. Single streaming pass over global memory.
//
// Inputs (metadata order = setup_inputs dict order):
//  0 dur_anchor_src   f32 [B,U]
//  1 unit_mask        f32 [B,U]
//  2 speech_budget_win f32 [B,1]
//  3 pause_budget_win  f32 [B,1]
//  4 dur_logratio_unit f32 [B,U]
//  5 pause_weight_unit f32 [B,U]
//  6 boundary_latent   f32 [B,U]
//  7 phase_ptr         f32 [B]
//  8 backlog           f32 [B]
//  9 clock_delta       f32 [B]
// 10 commit_frontier   i32 [B]
// 11 open_run_mask     i32 [B,U]
//
// Output (f32, concatenated flat in reference return order):
//  speech [B*U] | pause [B*U] | effective [B*U] | commit [B] | next_phase [B]
//  | next_backlog [B] | next_clock [B]

#define BS 256

__device__ __forceinline__ float warpSum(float v) {
    #pragma unroll
    for (int o = 16; o > 0; o >>= 1) v += __shfl_down_sync(0xffffffffu, v, o);
    return v;
}
__device__ __forceinline__ int warpMin(int v) {
    #pragma unroll
    for (int o = 16; o > 0; o >>= 1) v = min(v, __shfl_down_sync(0xffffffffu, v, o));
    return v;
}

template<int ITEMS>
__global__ __launch_bounds__(BS)
void rhythm_projector_kernel(
    const float* __restrict__ anchor_src,
    const float* __restrict__ unit_mask,
    const float* __restrict__ speech_budget,
    const float* __restrict__ pause_budget,
    const float* __restrict__ lr_unit,
    const float* __restrict__ pw_unit,
    const float* __restrict__ bl_unit,
    const float* __restrict__ phase_ptr,
    const float* __restrict__ backlog,
    const float* __restrict__ clock_delta,
    const int*   __restrict__ commit_frontier,
    const int*   __restrict__ open_run,
    float* __restrict__ out,
    int B, int U)
{
    const int row = blockIdx.x;
    const int tid = threadIdx.x;
    const size_t base = (size_t)row * (size_t)U;
    const size_t BU = (size_t)B * (size_t)U;

    __shared__ float s_f0[BS / 32];
    __shared__ float s_f1[BS / 32];
    __shared__ float s_f2[BS / 32];
    __shared__ int   s_i0[BS / 32];
    __shared__ float s_bcast[4];
    __shared__ int   s_ibcast[1];

    // ---------------- Pass A: load + elementwise + partial reductions --------
    float a_raw[ITEMS];   // dur_anchor_src
    float sp[ITEMS];      // unscaled masked speech
    float sc[ITEMS];      // pause scores
    float msk[ITEMS];     // unit_mask

    float sum_sp = 0.f, sum_sc = 0.f, sum_m = 0.f;
    int first_open = INT_MAX;

    #pragma unroll
    for (int k = 0; k < ITEMS; k++) {
        const int j = k * BS + tid;
        float ar = 0.f, m = 0.f, spv = 0.f, scv = 0.f;
        if (j < U) {
            ar        = anchor_src[base + j];
            m         = unit_mask[base + j];
            float lrv = lr_unit[base + j];
            float pwv = pw_unit[base + j];
            float blv = bl_unit[base + j];
            int   op  = open_run[base + j];

            float a    = fmaxf(ar, 1.0f);                 // MIN_SPEECH_FRAMES
            float bse  = a * __expf(lrv);
            spv = fmaxf(fminf(bse, a * 3.0f), 1.0f) * m;  // MAX_SPEECH_EXPAND
            scv = fmaxf(pwv, 0.f) * (0.5f + blv) * m;

            if (op > 0 && m > 0.f) first_open = min(first_open, j);
        }
        a_raw[k] = ar; sp[k] = spv; sc[k] = scv; msk[k] = m;
        sum_sp += spv; sum_sc += scv; sum_m += m;
    }

    // block reduction (deterministic tree)
    {
        float w0 = warpSum(sum_sp);
        float w1 = warpSum(sum_sc);
        float w2 = warpSum(sum_m);
        int   w3 = warpMin(first_open);
        const int wid = tid >> 5, lid = tid & 31;
        if (lid == 0) { s_f0[wid] = w0; s_f1[wid] = w1; s_f2[wid] = w2; s_i0[wid] = w3; }
        __syncthreads();
        if (wid == 0) {
            const int nw = BS / 32;
            float v0 = (lid < nw) ? s_f0[lid] : 0.f;
            float v1 = (lid < nw) ? s_f1[lid] : 0.f;
            float v2 = (lid < nw) ? s_f2[lid] : 0.f;
            int   v3 = (lid < nw) ? s_i0[lid] : INT_MAX;
            #pragma unroll
            for (int o = 4; o > 0; o >>= 1) {
                v0 += __shfl_down_sync(0xffffffffu, v0, o);
                v1 += __shfl_down_sync(0xffffffffu, v1, o);
                v2 += __shfl_down_sync(0xffffffffu, v2, o);
                v3 = min(v3, __shfl_down_sync(0xffffffffu, v3, o));
            }
            if (lid == 0) { s_bcast[0] = v0; s_bcast[1] = v1; s_bcast[2] = v2; s_ibcast[0] = v3; }
        }
        __syncthreads();
        sum_sp = s_bcast[0]; sum_sc = s_bcast[1]; sum_m = s_bcast[2];
        first_open = s_ibcast[0];
    }

    // ---------------- scalar frontier logic (all threads, uniform) ----------
    const float sbud = speech_budget[row];
    const float pbud = pause_budget[row];
    const float speech_scale = sbud / fmaxf(sum_sp, 1e-6f);

    const int  visible  = (int)sum_m;   // sum of exact 0/1 floats
    const bool has_open = (first_open != INT_MAX);
    const int  closed   = has_open ? first_open : visible;
    const int  cap      = max(visible - 2, 0);            // TAIL_HOLD_UNITS
    int cand = min(cap, closed);
    const int prev = commit_frontier[row];
    const int bidx = min(max(cand - 1, 0), U - 1);
    const float bval = bl_unit[base + bidx];              // uniform broadcast load
    const bool soft = (cand > 0) && (cand < visible) && (bval < 0.45f);
    if (soft) cand = max(prev, cand - 1);
    const int commit = max(prev, cand);

    const bool  use_scores = (sum_sc > 0.f);
    const float wdenom = 1.f / fmaxf(sum_sc, 1e-6f);
    const float fb     = 1.f / fmaxf(sum_m, 1.f);

    // ---------------- Pass B: outputs + commit-window sums -------------------
    float sum_eff = 0.f, exec_s = 0.f, src_s = 0.f;
    #pragma unroll
    for (int k = 0; k < ITEMS; k++) {
        const int j = k * BS + tid;
        if (j < U) {
            const float speech = sp[k] * speech_scale;
            const float w      = use_scores ? (sc[k] * wdenom) : (msk[k] * fb);
            const float pause  = w * pbud;
            const float eff    = (speech + pause) * msk[k];
            out[base + j]            = speech;
            out[BU + base + j]       = pause;
            out[2 * BU + base + j]   = eff;
            sum_eff += eff;
            if (j >= prev && j < commit) { exec_s += eff; src_s += a_raw[k]; }
        }
    }

    // final reduction of 3 sums
    {
        float w0 = warpSum(sum_eff);
        float w1 = warpSum(exec_s);
        float w2 = warpSum(src_s);
        const int wid = tid >> 5, lid = tid & 31;
        __syncthreads();  // protect smem reuse
        if (lid == 0) { s_f0[wid] = w0; s_f1[wid] = w1; s_f2[wid] = w2; }
        __syncthreads();
        if (wid == 0 && lid == 0) {
            float v0 = 0.f, v1 = 0.f, v2 = 0.f;
            #pragma unroll
            for (int i = 0; i < BS / 32; i++) { v0 += s_f0[i]; v1 += s_f1[i]; v2 += s_f2[i]; }

            const bool adv = commit > prev;
            const float cd = clock_delta[row];
            const float next_clock = adv ? (cd + (v1 - v2)) : cd;
            const float next_backlog = adv ? fmaxf(next_clock, 0.f) : backlog[row];
            const float vt = fmaxf(v0, 1.f);
            float next_phase = phase_ptr[row];
            if (adv) next_phase = fminf(fmaxf(next_phase + v1 / vt, 0.f), 1.f);

            float* tail = out + 3 * BU;
            tail[row]         = (float)commit;
            tail[B + row]     = next_phase;
            tail[2 * B + row] = next_backlog;
            tail[3 * B + row] = next_clock;
        }
    }
}

extern "C" void kernel_launch(void* const* d_in, const int* in_sizes, int n_in,
                              void* d_out, int out_size)
{
    const float* anchor_src  = (const float*)d_in[0];
    const float* unit_mask   = (const float*)d_in[1];
    const float* sbud        = (const float*)d_in[2];
    const float* pbud        = (const float*)d_in[3];
    const float* lr_unit     = (const float*)d_in[4];
    const float* pw_unit     = (const float*)d_in[5];
    const float* bl_unit     = (const float*)d_in[6];
    const float* phase_ptr   = (const float*)d_in[7];
    const float* backlog     = (const float*)d_in[8];
    const float* clock_delta = (const float*)d_in[9];
    const int*   frontier    = (const int*)d_in[10];
    const int*   open_run    = (const int*)d_in[11];
    float* out = (float*)d_out;

    const int B = in_sizes[2];            // speech_budget_win has B elements
    const int U = in_sizes[0] / B;        // dur_anchor_src has B*U

    const int items = (U + BS - 1) / BS;
    dim3 grid(B), block(BS);
    if (items <= 4) {
        rhythm_projector_kernel<4><<<grid, block>>>(anchor_src, unit_mask, sbud, pbud,
            lr_unit, pw_unit, bl_unit, phase_ptr, backlog, clock_delta, frontier,
            open_run, out, B, U);
    } else if (items <= 8) {
        rhythm_projector_kernel<8><<<grid, block>>>(anchor_src, unit_mask, sbud, pbud,
            lr_unit, pw_unit, bl_unit, phase_ptr, backlog, clock_delta, frontier,
            open_run, out, B, U);
    } else if (items <= 16) {
        rhythm_projector_kernel<16><<<grid, block>>>(anchor_src, unit_mask, sbud, pbud,
            lr_unit, pw_unit, bl_unit, phase_ptr, backlog, clock_delta, frontier,
            open_run, out, B, U);
    } else {
        rhythm_projector_kernel<32><<<grid, block>>>(anchor_src, unit_mask, sbud, pbud,
            lr_unit, pw_unit, bl_unit, phase_ptr, backlog, clock_delta, frontier,
            open_run, out, B, U);
    }
}

// round 3
// speedup vs baseline: 1.2519x; 1.2519x over previous
#include <cuda_runtime.h>
#include <cuda_bf16.h>
#include <limits.h>

// StreamingRhythmProjector on GB300 — vectorized float4 single-pass version.
//
// One block per row (B rows), BS=512 threads, IV float4 vectors per thread.
// For the benchmark shape (U=2048) each thread owns exactly one float4.
// Registers held across the mid-kernel barrier: sp4, sc4, m4 (12 regs) only;
// dur_anchor_src is re-loaded (L2 hit) inside the tiny commit window.
//
// Output (f32 flat): speech[B*U] | pause[B*U] | effective[B*U] |
//                    commit[B] | next_phase[B] | next_backlog[B] | next_clock[B]

#define BS 512
#define NW (BS / 32)

__device__ __forceinline__ float warpSum(float v) {
    #pragma unroll
    for (int o = 16; o > 0; o >>= 1) v += __shfl_down_sync(0xffffffffu, v, o);
    return v;
}
__device__ __forceinline__ int warpMin(int v) {
    #pragma unroll
    for (int o = 16; o > 0; o >>= 1) v = min(v, __shfl_down_sync(0xffffffffu, v, o));
    return v;
}

// ---------------------------------------------------------------------------
// Vectorized kernel (requires U % 4 == 0)
// ---------------------------------------------------------------------------
template<int IV>
__global__ __launch_bounds__(BS, 3)
void rhythm_projector_v2(
    const float* __restrict__ anchor_src,
    const float* __restrict__ unit_mask,
    const float* __restrict__ speech_budget,
    const float* __restrict__ pause_budget,
    const float* __restrict__ lr_unit,
    const float* __restrict__ pw_unit,
    const float* __restrict__ bl_unit,
    const float* __restrict__ phase_ptr,
    const float* __restrict__ backlog,
    const float* __restrict__ clock_delta,
    const int*   __restrict__ commit_frontier,
    const int*   __restrict__ open_run,
    float* __restrict__ out,
    int B, int U)
{
    const int row = blockIdx.x;
    const int tid = threadIdx.x;
    const size_t base = (size_t)row * (size_t)U;
    const size_t BU = (size_t)B * (size_t)U;

    __shared__ float s_f0[NW];
    __shared__ float s_f1[NW];
    __shared__ float s_f2[NW];
    __shared__ int   s_i0[NW];
    __shared__ float s_bcast[3];
    __shared__ int   s_ibcast;

    // ---------------- Pass A: vector load + elementwise + partial sums ------
    float4 sp[IV], sc[IV], mk[IV];
    float sum_sp = 0.f, sum_sc = 0.f, sum_m = 0.f;
    int first_open = INT_MAX;

    #pragma unroll
    for (int k = 0; k < IV; k++) {
        const int j = (k * BS + tid) * 4;
        float4 spv = make_float4(0.f, 0.f, 0.f, 0.f);
        float4 scv = spv, m4 = spv;
        if (j < U) {
            const float4 ar = *(const float4*)(anchor_src + base + j);
            m4              = *(const float4*)(unit_mask  + base + j);
            const float4 lr = *(const float4*)(lr_unit    + base + j);
            const float4 pw = *(const float4*)(pw_unit    + base + j);
            const float4 bl = *(const float4*)(bl_unit    + base + j);
            const int4   op = *(const int4*)(open_run     + base + j);

            #define ELEM(c, e)                                                   \
            {                                                                    \
                const float a = fmaxf(ar.c, 1.0f);                               \
                const float b = a * __expf(lr.c);                                \
                spv.c = fmaxf(fminf(b, a * 3.0f), 1.0f) * m4.c;                  \
                scv.c = fmaxf(pw.c, 0.f) * (0.5f + bl.c) * m4.c;                 \
                if (op.c > 0 && m4.c > 0.f) first_open = min(first_open, j + e); \
            }
            ELEM(x, 0) ELEM(y, 1) ELEM(z, 2) ELEM(w, 3)
            #undef ELEM

            sum_sp += (spv.x + spv.y) + (spv.z + spv.w);
            sum_sc += (scv.x + scv.y) + (scv.z + scv.w);
            sum_m  += (m4.x + m4.y) + (m4.z + m4.w);
        }
        sp[k] = spv; sc[k] = scv; mk[k] = m4;
    }

    // ---------------- block reduction (deterministic tree) ------------------
    {
        float w0 = warpSum(sum_sp);
        float w1 = warpSum(sum_sc);
        float w2 = warpSum(sum_m);
        int   w3 = warpMin(first_open);
        const int wid = tid >> 5, lid = tid & 31;
        if (lid == 0) { s_f0[wid] = w0; s_f1[wid] = w1; s_f2[wid] = w2; s_i0[wid] = w3; }
        __syncthreads();
        if (wid == 0) {
            float v0 = (lid < NW) ? s_f0[lid] : 0.f;
            float v1 = (lid < NW) ? s_f1[lid] : 0.f;
            float v2 = (lid < NW) ? s_f2[lid] : 0.f;
            int   v3 = (lid < NW) ? s_i0[lid] : INT_MAX;
            #pragma unroll
            for (int o = 8; o > 0; o >>= 1) {
                v0 += __shfl_down_sync(0xffffffffu, v0, o);
                v1 += __shfl_down_sync(0xffffffffu, v1, o);
                v2 += __shfl_down_sync(0xffffffffu, v2, o);
                v3 = min(v3, __shfl_down_sync(0xffffffffu, v3, o));
            }
            if (lid == 0) { s_bcast[0] = v0; s_bcast[1] = v1; s_bcast[2] = v2; s_ibcast = v3; }
        }
        __syncthreads();
        sum_sp = s_bcast[0]; sum_sc = s_bcast[1]; sum_m = s_bcast[2];
        first_open = s_ibcast;
    }

    // ---------------- scalar frontier logic (uniform across block) ----------
    const float sbud = speech_budget[row];
    const float pbud = pause_budget[row];
    const float speech_scale = sbud / fmaxf(sum_sp, 1e-6f);

    const int  visible  = (int)sum_m;            // exact: sum of 0/1 floats
    const bool has_open = (first_open != INT_MAX);
    const int  closed   = has_open ? first_open : visible;
    const int  cap      = max(visible - 2, 0);   // TAIL_HOLD_UNITS
    int cand = min(cap, closed);
    const int prev = commit_frontier[row];
    const int bidx = min(max(cand - 1, 0), U - 1);
    const float bval = __ldg(bl_unit + base + bidx);   // uniform broadcast
    const bool soft = (cand > 0) && (cand < visible) && (bval < 0.45f);
    if (soft) cand = max(prev, cand - 1);
    const int commit = max(prev, cand);

    const bool  use_scores = (sum_sc > 0.f);
    const float wdenom = 1.f / fmaxf(sum_sc, 1e-6f);
    const float fb     = 1.f / fmaxf(sum_m, 1.f);

    // ---------------- Pass B: compute + vector stores + window sums ---------
    float sum_eff = 0.f, exec_s = 0.f, src_s = 0.f;
    #pragma unroll
    for (int k = 0; k < IV; k++) {
        const int j = (k * BS + tid) * 4;
        if (j < U) {
            float4 speech, pause, eff;
            const float4 spv = sp[k], scv = sc[k], m4 = mk[k];

            #define ELEM(c, e)                                                     \
            {                                                                      \
                speech.c = spv.c * speech_scale;                                   \
                const float w = use_scores ? (scv.c * wdenom) : (m4.c * fb);       \
                pause.c = w * pbud;                                                \
                eff.c = (speech.c + pause.c) * m4.c;                               \
                sum_eff += eff.c;                                                  \
                const int je = j + e;                                              \
                if (je >= prev && je < commit) {                                   \
                    exec_s += eff.c;                                               \
                    src_s  += __ldg(anchor_src + base + je);                       \
                }                                                                  \
            }
            ELEM(x, 0) ELEM(y, 1) ELEM(z, 2) ELEM(w, 3)
            #undef ELEM

            *(float4*)(out + base + j)          = speech;
            *(float4*)(out + BU + base + j)     = pause;
            *(float4*)(out + 2 * BU + base + j) = eff;
        }
    }

    // ---------------- final 3-way reduction + tail outputs ------------------
    {
        float w0 = warpSum(sum_eff);
        float w1 = warpSum(exec_s);
        float w2 = warpSum(src_s);
        const int wid = tid >> 5, lid = tid & 31;
        if (lid == 0) { s_f0[wid] = w0; s_f1[wid] = w1; s_f2[wid] = w2; }
        __syncthreads();
        if (tid == 0) {
            float v0 = 0.f, v1 = 0.f, v2 = 0.f;
            #pragma unroll
            for (int i = 0; i < NW; i++) { v0 += s_f0[i]; v1 += s_f1[i]; v2 += s_f2[i]; }

            const bool adv = commit > prev;
            const float cd = clock_delta[row];
            const float next_clock = adv ? (cd + (v1 - v2)) : cd;
            const float next_backlog = adv ? fmaxf(next_clock, 0.f) : backlog[row];
            const float vt = fmaxf(v0, 1.f);
            float next_phase = phase_ptr[row];
            if (adv) next_phase = fminf(fmaxf(next_phase + v1 / vt, 0.f), 1.f);

            float* tail = out + 3 * BU;
            tail[row]         = (float)commit;
            tail[B + row]     = next_phase;
            tail[2 * B + row] = next_backlog;
            tail[3 * B + row] = next_clock;
        }
    }
}

// ---------------------------------------------------------------------------
// Scalar fallback kernel (any U)
// ---------------------------------------------------------------------------
template<int ITEMS>
__global__ __launch_bounds__(BS)
void rhythm_projector_scalar(
    const float* __restrict__ anchor_src,
    const float* __restrict__ unit_mask,
    const float* __restrict__ speech_budget,
    const float* __restrict__ pause_budget,
    const float* __restrict__ lr_unit,
    const float* __restrict__ pw_unit,
    const float* __restrict__ bl_unit,
    const float* __restrict__ phase_ptr,
    const float* __restrict__ backlog,
    const float* __restrict__ clock_delta,
    const int*   __restrict__ commit_frontier,
    const int*   __restrict__ open_run,
    float* __restrict__ out,
    int B, int U)
{
    const int row = blockIdx.x;
    const int tid = threadIdx.x;
    const size_t base = (size_t)row * (size_t)U;
    const size_t BU = (size_t)B * (size_t)U;

    __shared__ float s_f0[NW], s_f1[NW], s_f2[NW];
    __shared__ int   s_i0[NW];
    __shared__ float s_bcast[3];
    __shared__ int   s_ibcast;

    float sp[ITEMS], sc[ITEMS], msk[ITEMS];
    float sum_sp = 0.f, sum_sc = 0.f, sum_m = 0.f;
    int first_open = INT_MAX;

    #pragma unroll
    for (int k = 0; k < ITEMS; k++) {
        const int j = k * BS + tid;
        float m = 0.f, spv = 0.f, scv = 0.f;
        if (j < U) {
            const float ar  = anchor_src[base + j];
            m               = unit_mask[base + j];
            const float lrv = lr_unit[base + j];
            const float pwv = pw_unit[base + j];
            const float blv = bl_unit[base + j];
            const int   op  = open_run[base + j];
            const float a   = fmaxf(ar, 1.0f);
            const float b   = a * __expf(lrv);
            spv = fmaxf(fminf(b, a * 3.0f), 1.0f) * m;
            scv = fmaxf(pwv, 0.f) * (0.5f + blv) * m;
            if (op > 0 && m > 0.f) first_open = min(first_open, j);
        }
        sp[k] = spv; sc[k] = scv; msk[k] = m;
        sum_sp += spv; sum_sc += scv; sum_m += m;
    }

    {
        float w0 = warpSum(sum_sp), w1 = warpSum(sum_sc), w2 = warpSum(sum_m);
        int w3 = warpMin(first_open);
        const int wid = tid >> 5, lid = tid & 31;
        if (lid == 0) { s_f0[wid] = w0; s_f1[wid] = w1; s_f2[wid] = w2; s_i0[wid] = w3; }
        __syncthreads();
        if (wid == 0) {
            float v0 = (lid < NW) ? s_f0[lid] : 0.f;
            float v1 = (lid < NW) ? s_f1[lid] : 0.f;
            float v2 = (lid < NW) ? s_f2[lid] : 0.f;
            int   v3 = (lid < NW) ? s_i0[lid] : INT_MAX;
            #pragma unroll
            for (int o = 8; o > 0; o >>= 1) {
                v0 += __shfl_down_sync(0xffffffffu, v0, o);
                v1 += __shfl_down_sync(0xffffffffu, v1, o);
                v2 += __shfl_down_sync(0xffffffffu, v2, o);
                v3 = min(v3, __shfl_down_sync(0xffffffffu, v3, o));
            }
            if (lid == 0) { s_bcast[0] = v0; s_bcast[1] = v1; s_bcast[2] = v2; s_ibcast = v3; }
        }
        __syncthreads();
        sum_sp = s_bcast[0]; sum_sc = s_bcast[1]; sum_m = s_bcast[2];
        first_open = s_ibcast;
    }

    const float sbud = speech_budget[row];
    const float pbud = pause_budget[row];
    const float speech_scale = sbud / fmaxf(sum_sp, 1e-6f);
    const int  visible  = (int)sum_m;
    const bool has_open = (first_open != INT_MAX);
    const int  closed   = has_open ? first_open : visible;
    const int  cap      = max(visible - 2, 0);
    int cand = min(cap, closed);
    const int prev = commit_frontier[row];
    const int bidx = min(max(cand - 1, 0), U - 1);
    const float bval = __ldg(bl_unit + base + bidx);
    const bool soft = (cand > 0) && (cand < visible) && (bval < 0.45f);
    if (soft) cand = max(prev, cand - 1);
    const int commit = max(prev, cand);

    const bool  use_scores = (sum_sc > 0.f);
    const float wdenom = 1.f / fmaxf(sum_sc, 1e-6f);
    const float fb     = 1.f / fmaxf(sum_m, 1.f);

    float sum_eff = 0.f, exec_s = 0.f, src_s = 0.f;
    #pragma unroll
    for (int k = 0; k < ITEMS; k++) {
        const int j = k * BS + tid;
        if (j < U) {
            const float speech = sp[k] * speech_scale;
            const float w      = use_scores ? (sc[k] * wdenom) : (msk[k] * fb);
            const float pause  = w * pbud;
            const float eff    = (speech + pause) * msk[k];
            out[base + j]          = speech;
            out[BU + base + j]     = pause;
            out[2 * BU + base + j] = eff;
            sum_eff += eff;
            if (j >= prev && j < commit) {
                exec_s += eff;
                src_s  += __ldg(anchor_src + base + j);
            }
        }
    }

    {
        float w0 = warpSum(sum_eff), w1 = warpSum(exec_s), w2 = warpSum(src_s);
        const int wid = tid >> 5, lid = tid & 31;
        if (lid == 0) { s_f0[wid] = w0; s_f1[wid] = w1; s_f2[wid] = w2; }
        __syncthreads();
        if (tid == 0) {
            float v0 = 0.f, v1 = 0.f, v2 = 0.f;
            #pragma unroll
            for (int i = 0; i < NW; i++) { v0 += s_f0[i]; v1 += s_f1[i]; v2 += s_f2[i]; }
            const bool adv = commit > prev;
            const float cd = clock_delta[row];
            const float next_clock = adv ? (cd + (v1 - v2)) : cd;
            const float next_backlog = adv ? fmaxf(next_clock, 0.f) : backlog[row];
            const float vt = fmaxf(v0, 1.f);
            float next_phase = phase_ptr[row];
            if (adv) next_phase = fminf(fmaxf(next_phase + v1 / vt, 0.f), 1.f);
            float* tail = out + 3 * BU;
            tail[row]         = (float)commit;
            tail[B + row]     = next_phase;
            tail[2 * B + row] = next_backlog;
            tail[3 * B + row] = next_clock;
        }
    }
}

extern "C" void kernel_launch(void* const* d_in, const int* in_sizes, int n_in,
                              void* d_out, int out_size)
{
    const float* anchor_src  = (const float*)d_in[0];
    const float* unit_mask   = (const float*)d_in[1];
    const float* sbud        = (const float*)d_in[2];
    const float* pbud        = (const float*)d_in[3];
    const float* lr_unit     = (const float*)d_in[4];
    const float* pw_unit     = (const float*)d_in[5];
    const float* bl_unit     = (const float*)d_in[6];
    const float* phase_ptr   = (const float*)d_in[7];
    const float* backlog     = (const float*)d_in[8];
    const float* clock_delta = (const float*)d_in[9];
    const int*   frontier    = (const int*)d_in[10];
    const int*   open_run    = (const int*)d_in[11];
    float* out = (float*)d_out;

    const int B = in_sizes[2];            // speech_budget_win has B elements
    const int U = in_sizes[0] / B;        // dur_anchor_src has B*U

    dim3 grid(B), block(BS);

    if ((U & 3) == 0) {
        const int iv = (U + BS * 4 - 1) / (BS * 4);
        #define LAUNCH(N) rhythm_projector_v2<N><<<grid, block>>>(anchor_src,        \
            unit_mask, sbud, pbud, lr_unit, pw_unit, bl_unit, phase_ptr, backlog,    \
            clock_delta, frontier, open_run, out, B, U)
        if      (iv <= 1) LAUNCH(1);
        else if (iv <= 2) LAUNCH(2);
        else if (iv <= 4) LAUNCH(4);
        else              LAUNCH(8);
        #undef LAUNCH
    } else {
        const int items = (U + BS - 1) / BS;
        #define LAUNCH(N) rhythm_projector_scalar<N><<<grid, block>>>(anchor_src,    \
            unit_mask, sbud, pbud, lr_unit, pw_unit, bl_unit, phase_ptr, backlog,    \
            clock_delta, frontier, open_run, out, B, U)
        if      (items <= 4)  LAUNCH(4);
        else if (items <= 8)  LAUNCH(8);
        else if (items <= 16) LAUNCH(16);
        else                  LAUNCH(32);
        #undef LAUNCH
    }
}

// round 4
// speedup vs baseline: 1.2943x; 1.0338x over previous
#include <cuda_runtime.h>
#include <cuda_bf16.h>
#include <limits.h>

// StreamingRhythmProjector on GB300 — v3: smem-staged, 100%-occupancy version.
//
// One block per row, BS=512 threads, IV float4 per thread (IV=1 for U=2048).
// Pass A computes unscaled speech/score vectors and stages them in SMEM so no
// bulk state lives in registers across the reduction barrier -> <=32 regs ->
// 4 CTAs/SM (2048 threads, 100% occupancy). Pass B reads SMEM and streams the
// three outputs with .cs stores.
//
// Output (f32 flat): speech[B*U] | pause[B*U] | effective[B*U] |
//                    commit[B] | next_phase[B] | next_backlog[B] | next_clock[B]

#define BS 512
#define NW (BS / 32)

__device__ __forceinline__ float warpSum(float v) {
    #pragma unroll
    for (int o = 16; o > 0; o >>= 1) v += __shfl_down_sync(0xffffffffu, v, o);
    return v;
}
__device__ __forceinline__ int warpMin(int v) {
    #pragma unroll
    for (int o = 16; o > 0; o >>= 1) v = min(v, __shfl_down_sync(0xffffffffu, v, o));
    return v;
}

// ---------------------------------------------------------------------------
// Vectorized kernel (U % 4 == 0, IV <= 2 so static smem stays under 48KB)
// ---------------------------------------------------------------------------
template<int IV>
__global__ __launch_bounds__(BS, 4)
void rhythm_projector_v3(
    const float* __restrict__ anchor_src,
    const float* __restrict__ unit_mask,
    const float* __restrict__ speech_budget,
    const float* __restrict__ pause_budget,
    const float* __restrict__ lr_unit,
    const float* __restrict__ pw_unit,
    const float* __restrict__ bl_unit,
    const float* __restrict__ phase_ptr,
    const float* __restrict__ backlog,
    const float* __restrict__ clock_delta,
    const int*   __restrict__ commit_frontier,
    const int*   __restrict__ open_run,
    float* __restrict__ out,
    int B, int U)
{
    const int row = blockIdx.x;
    const int tid = threadIdx.x;
    const size_t base = (size_t)row * (size_t)U;
    const size_t BU = (size_t)B * (size_t)U;

    __shared__ float4 s_sp[BS * IV];
    __shared__ float4 s_sc[BS * IV];
    __shared__ float s_f0[NW], s_f1[NW], s_f2[NW];
    __shared__ int   s_i0[NW];
    __shared__ float s_bcast[3];
    __shared__ int   s_ibcast;

    // ---------------- Pass A: load + elementwise -> smem + partial sums -----
    float sum_sp = 0.f, sum_sc = 0.f, sum_m = 0.f;
    int first_open = INT_MAX;

    #pragma unroll
    for (int k = 0; k < IV; k++) {
        const int t = k * BS + tid;
        const int j = t * 4;
        float4 spv = make_float4(0.f, 0.f, 0.f, 0.f);
        float4 scv = spv;
        if (j < U) {
            const float4 ar = __ldcs((const float4*)(anchor_src + base + j));
            const float4 m4 = __ldcs((const float4*)(unit_mask  + base + j));
            const float4 lr = __ldcs((const float4*)(lr_unit    + base + j));
            const float4 pw = __ldcs((const float4*)(pw_unit    + base + j));
            const float4 bl = __ldcs((const float4*)(bl_unit    + base + j));
            const int4   op = __ldcs((const int4*)(open_run     + base + j));

            #define ELEM(c, e)                                                   \
            {                                                                    \
                const float a = fmaxf(ar.c, 1.0f);                               \
                const float b = a * __expf(lr.c);                                \
                spv.c = fmaxf(fminf(b, a * 3.0f), 1.0f) * m4.c;                  \
                scv.c = fmaxf(pw.c, 0.f) * (0.5f + bl.c) * m4.c;                 \
                if (op.c > 0 && m4.c > 0.f) first_open = min(first_open, j + e); \
            }
            ELEM(x, 0) ELEM(y, 1) ELEM(z, 2) ELEM(w, 3)
            #undef ELEM

            sum_sp += (spv.x + spv.y) + (spv.z + spv.w);
            sum_sc += (scv.x + scv.y) + (scv.z + scv.w);
            sum_m  += (m4.x + m4.y) + (m4.z + m4.w);
        }
        s_sp[t] = spv;
        s_sc[t] = scv;
    }

    // ---------------- block reduction (deterministic tree) ------------------
    {
        float w0 = warpSum(sum_sp);
        float w1 = warpSum(sum_sc);
        float w2 = warpSum(sum_m);
        int   w3 = warpMin(first_open);
        const int wid = tid >> 5, lid = tid & 31;
        if (lid == 0) { s_f0[wid] = w0; s_f1[wid] = w1; s_f2[wid] = w2; s_i0[wid] = w3; }
        __syncthreads();
        if (wid == 0) {
            float v0 = (lid < NW) ? s_f0[lid] : 0.f;
            float v1 = (lid < NW) ? s_f1[lid] : 0.f;
            float v2 = (lid < NW) ? s_f2[lid] : 0.f;
            int   v3 = (lid < NW) ? s_i0[lid] : INT_MAX;
            #pragma unroll
            for (int o = 8; o > 0; o >>= 1) {
                v0 += __shfl_down_sync(0xffffffffu, v0, o);
                v1 += __shfl_down_sync(0xffffffffu, v1, o);
                v2 += __shfl_down_sync(0xffffffffu, v2, o);
                v3 = min(v3, __shfl_down_sync(0xffffffffu, v3, o));
            }
            if (lid == 0) { s_bcast[0] = v0; s_bcast[1] = v1; s_bcast[2] = v2; s_ibcast = v3; }
        }
        __syncthreads();
        sum_sp = s_bcast[0]; sum_sc = s_bcast[1]; sum_m = s_bcast[2];
        first_open = s_ibcast;
    }

    // ---------------- scalar frontier logic (uniform across block) ----------
    const float sbud = speech_budget[row];
    const float pbud = pause_budget[row];
    const float speech_scale = sbud / fmaxf(sum_sp, 1e-6f);

    const int  visible  = (int)sum_m;            // exact: sum of 0/1 floats
    const bool has_open = (first_open != INT_MAX);
    const int  closed   = has_open ? first_open : visible;
    const int  cap      = max(visible - 2, 0);   // TAIL_HOLD_UNITS
    int cand = min(cap, closed);
    const int prev = commit_frontier[row];
    const int bidx = min(max(cand - 1, 0), U - 1);
    const float bval = __ldg(bl_unit + base + bidx);   // uniform broadcast
    const bool soft = (cand > 0) && (cand < visible) && (bval < 0.45f);
    if (soft) cand = max(prev, cand - 1);
    const int commit = max(prev, cand);

    const bool  use_scores = (sum_sc > 0.f);
    const float wdenom = pbud / fmaxf(sum_sc, 1e-6f);       // fold pbud in
    const float fb     = pbud / fmaxf(sum_m, 1.f);

    // ---------------- Pass B: compute + streaming stores + window sums ------
    float sum_eff = 0.f, exec_s = 0.f, src_s = 0.f;
    #pragma unroll
    for (int k = 0; k < IV; k++) {
        const int t = k * BS + tid;
        const int j = t * 4;
        if (j < U) {
            const float4 spv = s_sp[t];
            const float4 scv = s_sc[t];
            float4 speech, pause, eff;

            // speech and pause are both already mask-proportional (m in {0,1}),
            // so effective = speech + pause exactly. The fallback branch (only
            // when all scores are zero) uses the prefix-mask identity
            // m[j] = (j < visible).
            #define ELEM(c, e)                                                     \
            {                                                                      \
                speech.c = spv.c * speech_scale;                                   \
                pause.c = use_scores ? (scv.c * wdenom)                            \
                                     : (((j + e) < visible) ? fb : 0.f);           \
                eff.c = speech.c + pause.c;                                        \
                sum_eff += eff.c;                                                  \
                const int je = j + e;                                              \
                if (je >= prev && je < commit) {                                   \
                    exec_s += eff.c;                                               \
                    src_s  += __ldg(anchor_src + base + je);                       \
                }                                                                  \
            }
            ELEM(x, 0) ELEM(y, 1) ELEM(z, 2) ELEM(w, 3)
            #undef ELEM

            __stcs((float4*)(out + base + j),          speech);
            __stcs((float4*)(out + BU + base + j),     pause);
            __stcs((float4*)(out + 2 * BU + base + j), eff);
        }
    }

    // ---------------- final 3-way reduction + tail outputs ------------------
    {
        float w0 = warpSum(sum_eff);
        float w1 = warpSum(exec_s);
        float w2 = warpSum(src_s);
        const int wid = tid >> 5, lid = tid & 31;
        __syncthreads();   // s_f* reuse
        if (lid == 0) { s_f0[wid] = w0; s_f1[wid] = w1; s_f2[wid] = w2; }
        __syncthreads();
        if (tid == 0) {
            float v0 = 0.f, v1 = 0.f, v2 = 0.f;
            #pragma unroll
            for (int i = 0; i < NW; i++) { v0 += s_f0[i]; v1 += s_f1[i]; v2 += s_f2[i]; }

            const bool adv = commit > prev;
            const float cd = clock_delta[row];
            const float next_clock = adv ? (cd + (v1 - v2)) : cd;
            const float next_backlog = adv ? fmaxf(next_clock, 0.f) : backlog[row];
            const float vt = fmaxf(v0, 1.f);
            float next_phase = phase_ptr[row];
            if (adv) next_phase = fminf(fmaxf(next_phase + v1 / vt, 0.f), 1.f);

            float* tail = out + 3 * BU;
            tail[row]         = (float)commit;
            tail[B + row]     = next_phase;
            tail[2 * B + row] = next_backlog;
            tail[3 * B + row] = next_clock;
        }
    }
}

// ---------------------------------------------------------------------------
// Scalar fallback kernel (any U, register-held)
// ---------------------------------------------------------------------------
template<int ITEMS>
__global__ __launch_bounds__(BS)
void rhythm_projector_scalar(
    const float* __restrict__ anchor_src,
    const float* __restrict__ unit_mask,
    const float* __restrict__ speech_budget,
    const float* __restrict__ pause_budget,
    const float* __restrict__ lr_unit,
    const float* __restrict__ pw_unit,
    const float* __restrict__ bl_unit,
    const float* __restrict__ phase_ptr,
    const float* __restrict__ backlog,
    const float* __restrict__ clock_delta,
    const int*   __restrict__ commit_frontier,
    const int*   __restrict__ open_run,
    float* __restrict__ out,
    int B, int U)
{
    const int row = blockIdx.x;
    const int tid = threadIdx.x;
    const size_t base = (size_t)row * (size_t)U;
    const size_t BU = (size_t)B * (size_t)U;

    __shared__ float s_f0[NW], s_f1[NW], s_f2[NW];
    __shared__ int   s_i0[NW];
    __shared__ float s_bcast[3];
    __shared__ int   s_ibcast;

    float sp[ITEMS], sc[ITEMS], msk[ITEMS];
    float sum_sp = 0.f, sum_sc = 0.f, sum_m = 0.f;
    int first_open = INT_MAX;

    #pragma unroll
    for (int k = 0; k < ITEMS; k++) {
        const int j = k * BS + tid;
        float m = 0.f, spv = 0.f, scv = 0.f;
        if (j < U) {
            const float ar  = anchor_src[base + j];
            m               = unit_mask[base + j];
            const float lrv = lr_unit[base + j];
            const float pwv = pw_unit[base + j];
            const float blv = bl_unit[base + j];
            const int   op  = open_run[base + j];
            const float a   = fmaxf(ar, 1.0f);
            const float b   = a * __expf(lrv);
            spv = fmaxf(fminf(b, a * 3.0f), 1.0f) * m;
            scv = fmaxf(pwv, 0.f) * (0.5f + blv) * m;
            if (op > 0 && m > 0.f) first_open = min(first_open, j);
        }
        sp[k] = spv; sc[k] = scv; msk[k] = m;
        sum_sp += spv; sum_sc += scv; sum_m += m;
    }

    {
        float w0 = warpSum(sum_sp), w1 = warpSum(sum_sc), w2 = warpSum(sum_m);
        int w3 = warpMin(first_open);
        const int wid = tid >> 5, lid = tid & 31;
        if (lid == 0) { s_f0[wid] = w0; s_f1[wid] = w1; s_f2[wid] = w2; s_i0[wid] = w3; }
        __syncthreads();
        if (wid == 0) {
            float v0 = (lid < NW) ? s_f0[lid] : 0.f;
            float v1 = (lid < NW) ? s_f1[lid] : 0.f;
            float v2 = (lid < NW) ? s_f2[lid] : 0.f;
            int   v3 = (lid < NW) ? s_i0[lid] : INT_MAX;
            #pragma unroll
            for (int o = 8; o > 0; o >>= 1) {
                v0 += __shfl_down_sync(0xffffffffu, v0, o);
                v1 += __shfl_down_sync(0xffffffffu, v1, o);
                v2 += __shfl_down_sync(0xffffffffu, v2, o);
                v3 = min(v3, __shfl_down_sync(0xffffffffu, v3, o));
            }
            if (lid == 0) { s_bcast[0] = v0; s_bcast[1] = v1; s_bcast[2] = v2; s_ibcast = v3; }
        }
        __syncthreads();
        sum_sp = s_bcast[0]; sum_sc = s_bcast[1]; sum_m = s_bcast[2];
        first_open = s_ibcast;
    }

    const float sbud = speech_budget[row];
    const float pbud = pause_budget[row];
    const float speech_scale = sbud / fmaxf(sum_sp, 1e-6f);
    const int  visible  = (int)sum_m;
    const bool has_open = (first_open != INT_MAX);
    const int  closed   = has_open ? first_open : visible;
    const int  cap      = max(visible - 2, 0);
    int cand = min(cap, closed);
    const int prev = commit_frontier[row];
    const int bidx = min(max(cand - 1, 0), U - 1);
    const float bval = __ldg(bl_unit + base + bidx);
    const bool soft = (cand > 0) && (cand < visible) && (bval < 0.45f);
    if (soft) cand = max(prev, cand - 1);
    const int commit = max(prev, cand);

    const bool  use_scores = (sum_sc > 0.f);
    const float wdenom = 1.f / fmaxf(sum_sc, 1e-6f);
    const float fb     = 1.f / fmaxf(sum_m, 1.f);

    float sum_eff = 0.f, exec_s = 0.f, src_s = 0.f;
    #pragma unroll
    for (int k = 0; k < ITEMS; k++) {
        const int j = k * BS + tid;
        if (j < U) {
            const float speech = sp[k] * speech_scale;
            const float w      = use_scores ? (sc[k] * wdenom) : (msk[k] * fb);
            const float pause  = w * pbud;
            const float eff    = (speech + pause) * msk[k];
            out[base + j]          = speech;
            out[BU + base + j]     = pause;
            out[2 * BU + base + j] = eff;
            sum_eff += eff;
            if (j >= prev && j < commit) {
                exec_s += eff;
                src_s  += __ldg(anchor_src + base + j);
            }
        }
    }

    {
        float w0 = warpSum(sum_eff), w1 = warpSum(exec_s), w2 = warpSum(src_s);
        const int wid = tid >> 5, lid = tid & 31;
        if (lid == 0) { s_f0[wid] = w0; s_f1[wid] = w1; s_f2[wid] = w2; }
        __syncthreads();
        if (tid == 0) {
            float v0 = 0.f, v1 = 0.f, v2 = 0.f;
            #pragma unroll
            for (int i = 0; i < NW; i++) { v0 += s_f0[i]; v1 += s_f1[i]; v2 += s_f2[i]; }
            const bool adv = commit > prev;
            const float cd = clock_delta[row];
            const float next_clock = adv ? (cd + (v1 - v2)) : cd;
            const float next_backlog = adv ? fmaxf(next_clock, 0.f) : backlog[row];
            const float vt = fmaxf(v0, 1.f);
            float next_phase = phase_ptr[row];
            if (adv) next_phase = fminf(fmaxf(next_phase + v1 / vt, 0.f), 1.f);
            float* tail = out + 3 * BU;
            tail[row]         = (float)commit;
            tail[B + row]     = next_phase;
            tail[2 * B + row] = next_backlog;
            tail[3 * B + row] = next_clock;
        }
    }
}

extern "C" void kernel_launch(void* const* d_in, const int* in_sizes, int n_in,
                              void* d_out, int out_size)
{
    const float* anchor_src  = (const float*)d_in[0];
    const float* unit_mask   = (const float*)d_in[1];
    const float* sbud        = (const float*)d_in[2];
    const float* pbud        = (const float*)d_in[3];
    const float* lr_unit     = (const float*)d_in[4];
    const float* pw_unit     = (const float*)d_in[5];
    const float* bl_unit     = (const float*)d_in[6];
    const float* phase_ptr   = (const float*)d_in[7];
    const float* backlog     = (const float*)d_in[8];
    const float* clock_delta = (const float*)d_in[9];
    const int*   frontier    = (const int*)d_in[10];
    const int*   open_run    = (const int*)d_in[11];
    float* out = (float*)d_out;

    const int B = in_sizes[2];            // speech_budget_win has B elements
    const int U = in_sizes[0] / B;        // dur_anchor_src has B*U

    dim3 grid(B), block(BS);
    const int iv = (U + BS * 4 - 1) / (BS * 4);

    if ((U & 3) == 0 && iv <= 2) {
        #define LAUNCH(N) rhythm_projector_v3<N><<<grid, block>>>(anchor_src,        \
            unit_mask, sbud, pbud, lr_unit, pw_unit, bl_unit, phase_ptr, backlog,    \
            clock_delta, frontier, open_run, out, B, U)
        if (iv <= 1) LAUNCH(1);
        else         LAUNCH(2);
        #undef LAUNCH
    } else {
        const int items = (U + BS - 1) / BS;
        #define LAUNCH(N) rhythm_projector_scalar<N><<<grid, block>>>(anchor_src,    \
            unit_mask, sbud, pbud, lr_unit, pw_unit, bl_unit, phase_ptr, backlog,    \
            clock_delta, frontier, open_run, out, B, U)
        if      (items <= 4)  LAUNCH(4);
        else if (items <= 8)  LAUNCH(8);
        else if (items <= 16) LAUNCH(16);
        else                  LAUNCH(32);
        #undef LAUNCH
    }
}